// round 2
// baseline (speedup 1.0000x reference)
#include <cuda_runtime.h>

// ---------------------------------------------------------------------------
// 21 static anchor configs (hand-evaluated from the Python double math):
//   p3 (stride 32, grid 14): (74,49)(60,60)(49,74)(93,62)(76,76)(62,93)
//   p4 (stride 64, grid 7):  (148,98)(120,120)(98,148)(186,124)(152,152)(124,186)
//   p5 (stride 128, grid 4): (235,156)(192,192)(156,235)(296,197)(241,241)
//                            (197,296)(373,248)(304,304)(248,373)
// padding = ceil((k - stride)/2) = (k - stride + 1) >> 1  (k > stride always)
// ---------------------------------------------------------------------------
#define NCFG 21

__constant__ int c_kh[NCFG] = {74,60,49,93,76,62, 148,120,98,186,152,124,
                               235,192,156,296,241,197,373,304,248};
__constant__ int c_kw[NCFG] = {49,60,74,62,76,93, 98,120,148,124,152,186,
                               156,192,235,197,241,296,248,304,373};
// cumulative kh*kw offsets (elements per (bk,c) plane unit)
__constant__ int c_off[NCFG] = {0,3626,7226,10852,16618,22394,
                                28160,42664,57064,71568,94632,117736,
                                140800,177460,214324,250984,309296,367377,
                                425689,518193,610609};
// total area = 703113 ; scratch = 703113 * 32(bk) * 3(c) floats
#define TOTAL_AGG_FLOATS 67498848
__device__ float g_agg[TOTAL_AGG_FLOATS];

// ---------------------------------------------------------------------------
// Kernel A: agg[cfg][bk][i][j][c] = sum_{g,h} w[b,k,g,h] * x[b, g*s+i-p0, h*s+j-p1, c]
// grid: (ceil(max_area/256)=362, B=8, 21). Thread = (i,j) of one (cfg,b),
// accumulating all 4 k and 3 channels (12 regs) per x load.
// ---------------------------------------------------------------------------
__global__ void agg_kernel(const float* __restrict__ x,
                           const float* __restrict__ w3,
                           const float* __restrict__ w4,
                           const float* __restrict__ w5) {
    const int cfg = blockIdx.z;
    const int kh = c_kh[cfg], kw = c_kw[cfg];
    const int area = kh * kw;
    if ((int)(blockIdx.x * blockDim.x) >= area) return;  // uniform early exit

    int s, G, A, a;
    const float* wsrc;
    if (cfg < 6)       { s = 32;  G = 14; A = 6; a = cfg;      wsrc = w3; }
    else if (cfg < 12) { s = 64;  G = 7;  A = 6; a = cfg - 6;  wsrc = w4; }
    else               { s = 128; G = 4;  A = 9; a = cfg - 12; wsrc = w5; }

    const int b  = blockIdx.y;
    const int G2 = G * G;

    extern __shared__ float sw[];  // [k][g][h], 4*G2 floats (<= 784)
    const float* wb = wsrc + (size_t)(b * A + a) * 4 * G2;
    for (int t = threadIdx.x; t < 4 * G2; t += blockDim.x) sw[t] = wb[t];
    __syncthreads();

    const int idx = blockIdx.x * blockDim.x + threadIdx.x;
    if (idx >= area) return;

    const int i = idx / kw;
    const int j = idx - i * kw;
    const int p0 = (kh - s + 1) >> 1;
    const int p1 = (kw - s + 1) >> 1;
    const int ri = i - p0;   // x row = g*s + ri
    const int cj = j - p1;   // x col = h*s + cj

    const int gmin = (ri >= 0) ? 0 : (-ri + s - 1) / s;
    const int gmax = min(G - 1, (447 - ri) / s);
    const int hmin = (cj >= 0) ? 0 : (-cj + s - 1) / s;
    const int hmax = min(G - 1, (447 - cj) / s);

    float acc[12];
#pragma unroll
    for (int t = 0; t < 12; ++t) acc[t] = 0.0f;

    for (int g = gmin; g <= gmax; ++g) {
        const float* xrow = x + ((size_t)(b * 448 + g * s + ri)) * (448 * 3);
        const float* swg  = sw + g * G;
        for (int h = hmin; h <= hmax; ++h) {
            const float* xp = xrow + (h * s + cj) * 3;
            const float x0 = xp[0], x1 = xp[1], x2 = xp[2];
#pragma unroll
            for (int k = 0; k < 4; ++k) {
                const float wv = swg[k * G2 + h];
                acc[k * 3 + 0] += wv * x0;
                acc[k * 3 + 1] += wv * x1;
                acc[k * 3 + 2] += wv * x2;
            }
        }
    }

    float* dst = g_agg + (size_t)96 * c_off[cfg]
                       + ((size_t)(b * 4) * area + idx) * 3;
#pragma unroll
    for (int k = 0; k < 4; ++k) {
        float* d = dst + (size_t)k * area * 3;
        d[0] = acc[k * 3 + 0];
        d[1] = acc[k * 3 + 1];
        d[2] = acc[k * 3 + 2];
    }
}

// ---------------------------------------------------------------------------
// Bilinear (triangle, antialias=True, translation=0) taps for resize n -> 224.
// Matches jax.image.resize: sample_f=(o+0.5)*n/224-0.5, kernel_scale=max(n/224,1),
// weights renormalized over in-bounds taps.
// ---------------------------------------------------------------------------
__device__ __forceinline__ int make_taps(int n, int o, float* w, int* pcnt) {
    const float inv = (float)n * (1.0f / 224.0f);
    const float ks  = fmaxf(inv, 1.0f);
    const float sf  = ((float)o + 0.5f) * inv - 0.5f;
    int lo = (int)ceilf(sf - ks);
    int hi = (int)floorf(sf + ks);
    if (lo < 0) lo = 0;
    if (hi > n - 1) hi = n - 1;
    int cnt = hi - lo + 1;
    if (cnt > 5) cnt = 5;      // radius <= 1.666 -> cnt <= 4; safety clamp
    const float rks = 1.0f / ks;
    float tot = 0.0f;
#pragma unroll 5
    for (int t = 0; t < cnt; ++t) {
        float v = 1.0f - fabsf(sf - (float)(lo + t)) * rks;
        v = fmaxf(v, 0.0f);
        w[t] = v;
        tot += v;
    }
    const float r = 1.0f / tot;
#pragma unroll 5
    for (int t = 0; t < cnt; ++t) w[t] *= r;
    *pcnt = cnt;
    return lo;
}

// ---------------------------------------------------------------------------
// Kernel B: out[bk,oy,ox,c] = sum_cfg sum_{ty,tx} wy*wx * agg[cfg][bk][iy][jx][c]
// grid: (224 oy, 32 bk), block: 224 threads (ox). Row taps shared per block.
// ---------------------------------------------------------------------------
__global__ void resize_kernel(float* __restrict__ out) {
    const int oy = blockIdx.x;
    const int bk = blockIdx.y;
    const int ox = threadIdx.x;

    __shared__ float s_wr[NCFG][5];
    __shared__ int   s_r0[NCFG];
    __shared__ int   s_nr[NCFG];

    if (threadIdx.x < NCFG) {
        const int cfg = threadIdx.x;
        int nr;
        s_r0[cfg] = make_taps(c_kh[cfg], oy, s_wr[cfg], &nr);
        s_nr[cfg] = nr;
    }
    __syncthreads();

    float a0 = 0.0f, a1 = 0.0f, a2 = 0.0f;

    for (int cfg = 0; cfg < NCFG; ++cfg) {
        const int kw = c_kw[cfg];
        const int kh = c_kh[cfg];
        const int area = kh * kw;

        float wc[5];
        int nc;
        const int c0 = make_taps(kw, ox, wc, &nc);

        const float* base = g_agg + (size_t)96 * c_off[cfg]
                                  + (size_t)bk * area * 3;
        const int nr = s_nr[cfg];
        const int r0 = s_r0[cfg];

        for (int ty = 0; ty < nr; ++ty) {
            const float wy = s_wr[cfg][ty];
            const float* row = base + (size_t)(r0 + ty) * kw * 3 + (size_t)c0 * 3;
            for (int tx = 0; tx < nc; ++tx) {
                const float w = wy * wc[tx];
                a0 += w * row[tx * 3 + 0];
                a1 += w * row[tx * 3 + 1];
                a2 += w * row[tx * 3 + 2];
            }
        }
    }

    float* o = out + ((size_t)(bk * 224 + oy) * 224 + ox) * 3;
    o[0] = a0;
    o[1] = a1;
    o[2] = a2;
}

// ---------------------------------------------------------------------------
extern "C" void kernel_launch(void* const* d_in, const int* in_sizes, int n_in,
                              void* d_out, int out_size) {
    const float* x  = (const float*)d_in[0];
    const float* w3 = (const float*)d_in[1];
    const float* w4 = (const float*)d_in[2];
    const float* w5 = (const float*)d_in[3];

    // max area = 373*248 = 92504 -> ceil(92504/256) = 362 blocks
    dim3 gridA(362, 8, NCFG);
    agg_kernel<<<gridA, 256, 4 * 196 * sizeof(float)>>>(x, w3, w4, w5);

    dim3 gridB(224, 32);
    resize_kernel<<<gridB, 224>>>((float*)d_out);
}

// round 3
// speedup vs baseline: 1.2081x; 1.2081x over previous
#include <cuda_runtime.h>

#define NCFG 21

// (kh,kw) per cfg, padding = (k - stride + 1) >> 1
__constant__ int c_kh[NCFG] = {74,60,49,93,76,62, 148,120,98,186,152,124,
                               235,192,156,296,241,197,373,304,248};
__constant__ int c_kw[NCFG] = {49,60,74,62,76,93, 98,120,148,124,152,186,
                               156,192,235,197,241,296,248,304,373};
__constant__ int c_off[NCFG] = {0,3626,7226,10852,16618,22394,
                                28160,42664,57064,71568,94632,117736,
                                140800,177460,214324,250984,309296,367377,
                                425689,518193,610609};
// total area = 703113 pixels; scratch layout: [cfg][bk(32)][pixel] as float4 (c padded)
#define TOTAL_AGG_F4 22499616
__device__ float4 g_agg4[TOTAL_AGG_F4];

// Tap tables: [cfg][o] -> 4 weights + 4 premultiplied offsets
__device__ float4 g_tyw[NCFG][224];
__device__ int4   g_tyo[NCFG][224];   // row offsets, premultiplied by kw (float4 units)
__device__ float4 g_txw[NCFG][224];
__device__ int4   g_txo[NCFG][224];   // column offsets (float4 units)

// ---------------------------------------------------------------------------
// Setup: exact jax.image.resize bilinear(antialias) taps, double precision.
// grid (21, 2), 224 threads. dim 0 = rows (kh), dim 1 = cols (kw).
// ---------------------------------------------------------------------------
__global__ void tap_kernel() {
    const int o   = threadIdx.x;
    const int cfg = blockIdx.x;
    const int dim = blockIdx.y;
    const int n   = dim ? c_kw[cfg] : c_kh[cfg];
    const int kw  = c_kw[cfg];

    const double ks = (n > 224) ? (double)n / 224.0 : 1.0;
    const double sf = ((double)o + 0.5) * (double)n / 224.0 - 0.5;
    const int NT = (n < 224) ? 2 : (2 * n) / 224 + 1;   // 2..4
    int lo = (int)ceil(sf - ks);

    double w[4];
    double tot = 0.0;
    for (int t = 0; t < 4; ++t) {
        double v = 0.0;
        if (t < NT) {
            int j = lo + t;
            if (j >= 0 && j < n) {
                v = 1.0 - fabs(sf - (double)j) / ks;
                if (v < 0.0) v = 0.0;
            }
        }
        w[t] = v;
        tot += v;
    }
    const double r = 1.0 / tot;

    float  wf[4];
    int    of[4];
    for (int t = 0; t < 4; ++t) {
        wf[t] = (float)(w[t] * r);
        int j = lo + t;
        if (j < 0) j = 0;
        if (j > n - 1) j = n - 1;
        of[t] = dim ? j : j * kw;
    }
    if (dim == 0) {
        g_tyw[cfg][o] = make_float4(wf[0], wf[1], wf[2], wf[3]);
        g_tyo[cfg][o] = make_int4(of[0], of[1], of[2], of[3]);
    } else {
        g_txw[cfg][o] = make_float4(wf[0], wf[1], wf[2], wf[3]);
        g_txo[cfg][o] = make_int4(of[0], of[1], of[2], of[3]);
    }
}

// ---------------------------------------------------------------------------
// Kernel A: agg[cfg][b*4+k][i][j] = sum_{g,h} w[b,k,g,h] * x[b, g*s+i-p0, h*s+j-p1, :]
// float4 stores (channel padded).
// ---------------------------------------------------------------------------
__global__ void agg_kernel(const float* __restrict__ x,
                           const float* __restrict__ w3,
                           const float* __restrict__ w4,
                           const float* __restrict__ w5) {
    const int cfg = blockIdx.z;
    const int kh = c_kh[cfg], kw = c_kw[cfg];
    const int area = kh * kw;
    if ((int)(blockIdx.x * blockDim.x) >= area) return;

    int s, G, A, a;
    const float* wsrc;
    if (cfg < 6)       { s = 32;  G = 14; A = 6; a = cfg;      wsrc = w3; }
    else if (cfg < 12) { s = 64;  G = 7;  A = 6; a = cfg - 6;  wsrc = w4; }
    else               { s = 128; G = 4;  A = 9; a = cfg - 12; wsrc = w5; }

    const int b  = blockIdx.y;
    const int G2 = G * G;

    extern __shared__ float sw[];  // [k][g][h]
    const float* wb = wsrc + (size_t)(b * A + a) * 4 * G2;
    for (int t = threadIdx.x; t < 4 * G2; t += blockDim.x) sw[t] = wb[t];
    __syncthreads();

    const int idx = blockIdx.x * blockDim.x + threadIdx.x;
    if (idx >= area) return;

    const int i = idx / kw;
    const int j = idx - i * kw;
    const int p0 = (kh - s + 1) >> 1;
    const int p1 = (kw - s + 1) >> 1;
    const int ri = i - p0;
    const int cj = j - p1;

    const int gmin = (ri >= 0) ? 0 : (-ri + s - 1) / s;
    const int gmax = min(G - 1, (447 - ri) / s);
    const int hmin = (cj >= 0) ? 0 : (-cj + s - 1) / s;
    const int hmax = min(G - 1, (447 - cj) / s);

    float acc[12];
#pragma unroll
    for (int t = 0; t < 12; ++t) acc[t] = 0.0f;

    for (int g = gmin; g <= gmax; ++g) {
        const float* xrow = x + ((size_t)(b * 448 + g * s + ri)) * (448 * 3);
        const float* swg  = sw + g * G;
        for (int h = hmin; h <= hmax; ++h) {
            const float* xp = xrow + (h * s + cj) * 3;
            const float x0 = xp[0], x1 = xp[1], x2 = xp[2];
#pragma unroll
            for (int k = 0; k < 4; ++k) {
                const float wv = swg[k * G2 + h];
                acc[k * 3 + 0] += wv * x0;
                acc[k * 3 + 1] += wv * x1;
                acc[k * 3 + 2] += wv * x2;
            }
        }
    }

    float4* dst = g_agg4 + (size_t)32 * c_off[cfg] + (size_t)(b * 4) * area + idx;
#pragma unroll
    for (int k = 0; k < 4; ++k) {
        dst[(size_t)k * area] =
            make_float4(acc[k * 3 + 0], acc[k * 3 + 1], acc[k * 3 + 2], 0.0f);
    }
}

// ---------------------------------------------------------------------------
// Kernel B: fully unrolled per-cfg separable resize accumulation.
// ---------------------------------------------------------------------------
template<int AREA, int OFF, int NR, int NC>
__device__ __forceinline__ void do_cfg(int cfg, int bk, int ox,
                                       const float (*s_yw)[4], const int (*s_yo)[4],
                                       float& a0, float& a1, float& a2) {
    const float4* base = g_agg4 + (size_t)32 * OFF + (size_t)bk * AREA;
    const float4 xw = g_txw[cfg][ox];
    const int4   xo = g_txo[cfg][ox];
    const float xwv[4] = {xw.x, xw.y, xw.z, xw.w};
    const int   xov[4] = {xo.x, xo.y, xo.z, xo.w};
#pragma unroll
    for (int r = 0; r < NR; ++r) {
        const float wy = s_yw[cfg][r];
        const float4* p = base + s_yo[cfg][r];
#pragma unroll
        for (int c = 0; c < NC; ++c) {
            const float w = wy * xwv[c];
            const float4 v = __ldg(p + xov[c]);
            a0 += w * v.x;
            a1 += w * v.y;
            a2 += w * v.z;
        }
    }
}

__global__ void __launch_bounds__(224) resize_kernel(float* __restrict__ out) {
    const int oy = blockIdx.x;
    const int bk = blockIdx.y;
    const int ox = threadIdx.x;

    __shared__ float s_yw[NCFG][4];
    __shared__ int   s_yo[NCFG][4];
    {
        const int t = threadIdx.x;
        if (t < NCFG * 4) {
            const int cfg = t >> 2, k = t & 3;
            s_yw[cfg][k] = ((const float*)&g_tyw[cfg][oy])[k];
            s_yo[cfg][k] = ((const int*)&g_tyo[cfg][oy])[k];
        }
    }
    __syncthreads();

    float a0 = 0.0f, a1 = 0.0f, a2 = 0.0f;

    do_cfg< 3626,      0, 2, 2>( 0, bk, ox, s_yw, s_yo, a0, a1, a2);
    do_cfg< 3600,   3626, 2, 2>( 1, bk, ox, s_yw, s_yo, a0, a1, a2);
    do_cfg< 3626,   7226, 2, 2>( 2, bk, ox, s_yw, s_yo, a0, a1, a2);
    do_cfg< 5766,  10852, 2, 2>( 3, bk, ox, s_yw, s_yo, a0, a1, a2);
    do_cfg< 5776,  16618, 2, 2>( 4, bk, ox, s_yw, s_yo, a0, a1, a2);
    do_cfg< 5766,  22394, 2, 2>( 5, bk, ox, s_yw, s_yo, a0, a1, a2);
    do_cfg<14504,  28160, 2, 2>( 6, bk, ox, s_yw, s_yo, a0, a1, a2);
    do_cfg<14400,  42664, 2, 2>( 7, bk, ox, s_yw, s_yo, a0, a1, a2);
    do_cfg<14504,  57064, 2, 2>( 8, bk, ox, s_yw, s_yo, a0, a1, a2);
    do_cfg<23064,  71568, 2, 2>( 9, bk, ox, s_yw, s_yo, a0, a1, a2);
    do_cfg<23104,  94632, 2, 2>(10, bk, ox, s_yw, s_yo, a0, a1, a2);
    do_cfg<23064, 117736, 2, 2>(11, bk, ox, s_yw, s_yo, a0, a1, a2);
    do_cfg<36660, 140800, 3, 2>(12, bk, ox, s_yw, s_yo, a0, a1, a2);
    do_cfg<36864, 177460, 2, 2>(13, bk, ox, s_yw, s_yo, a0, a1, a2);
    do_cfg<36660, 214324, 2, 3>(14, bk, ox, s_yw, s_yo, a0, a1, a2);
    do_cfg<58312, 250984, 3, 2>(15, bk, ox, s_yw, s_yo, a0, a1, a2);
    do_cfg<58081, 309296, 3, 3>(16, bk, ox, s_yw, s_yo, a0, a1, a2);
    do_cfg<58312, 367377, 2, 3>(17, bk, ox, s_yw, s_yo, a0, a1, a2);
    do_cfg<92504, 425689, 4, 3>(18, bk, ox, s_yw, s_yo, a0, a1, a2);
    do_cfg<92416, 518193, 3, 3>(19, bk, ox, s_yw, s_yo, a0, a1, a2);
    do_cfg<92504, 610609, 3, 4>(20, bk, ox, s_yw, s_yo, a0, a1, a2);

    float* o = out + ((size_t)(bk * 224 + oy) * 224 + ox) * 3;
    o[0] = a0;
    o[1] = a1;
    o[2] = a2;
}

// ---------------------------------------------------------------------------
extern "C" void kernel_launch(void* const* d_in, const int* in_sizes, int n_in,
                              void* d_out, int out_size) {
    const float* x  = (const float*)d_in[0];
    const float* w3 = (const float*)d_in[1];
    const float* w4 = (const float*)d_in[2];
    const float* w5 = (const float*)d_in[3];

    dim3 gridT(NCFG, 2);
    tap_kernel<<<gridT, 224>>>();

    dim3 gridA(362, 8, NCFG);   // ceil(92504/256)=362
    agg_kernel<<<gridA, 256, 4 * 196 * sizeof(float)>>>(x, w3, w4, w5);

    dim3 gridB(224, 32);
    resize_kernel<<<gridB, 224>>>((float*)d_out);
}